// round 5
// baseline (speedup 1.0000x reference)
#include <cuda_runtime.h>
#include <cuda_bf16.h>

// SmoothnessLoss: loss = mean_i( (sHat_i - sY_i)^2 ), i in [0, W), W = N-k-1
// s_i = sum_{j<k} | x[i+j] - mean_j |, k = 64.
// Persistent kernel, NO smem staging: each thread streams its 68-float segment
// directly from gmem (L1-resident due to 64-element overlap between neighbors).
// No barriers in the main loop. Fused deterministic final reduction.

#define K_WIN 64
#define BLOCK 256
#define WPT 4
#define STRIDE (BLOCK * WPT)                 // 1024 windows per iteration
#define CHUNKS 17                            // 16B chunks per segment (68 floats)
#define GRID 296                             // 2 blocks/SM x 148 SMs

typedef unsigned long long u64;

__device__ float g_partials[GRID];
__device__ unsigned int g_count = 0;

__device__ __forceinline__ u64 addx2(u64 a, u64 b) {
    u64 r; asm("add.rn.f32x2 %0, %1, %2;" : "=l"(r) : "l"(a), "l"(b)); return r;
}
__device__ __forceinline__ u64 pk(float lo, float hi) {
    u64 r; asm("mov.b64 %0, {%1, %2};" : "=l"(r) : "f"(lo), "f"(hi)); return r;
}
__device__ __forceinline__ void upk(u64 p, float& lo, float& hi) {
    asm("mov.b64 {%0, %1}, %2;" : "=f"(lo), "=f"(hi) : "l"(p));
}
__device__ __forceinline__ u64 absx2(u64 a) { return a & 0x7FFFFFFF7FFFFFFFULL; }

// Load 68 floats (34 packed pairs) starting at p (16B-aligned). rem = elements
// remaining in the array from p; zero-fill past the end (only feeds windows
// that are masked out at accumulation).
__device__ __forceinline__ void load_seg(const float* __restrict__ p, int rem,
                                         u64 v[2 * CHUNKS])
{
    if (rem >= 4 * CHUNKS) {
        const ulonglong2* p2 = reinterpret_cast<const ulonglong2*>(p);
        #pragma unroll
        for (int q = 0; q < CHUNKS; q++) {
            ulonglong2 c = p2[q];
            v[2 * q]     = c.x;
            v[2 * q + 1] = c.y;
        }
    } else {
        #pragma unroll
        for (int q = 0; q < 2 * CHUNKS; q++) {
            float lo = (2 * q     < rem) ? p[2 * q]     : 0.0f;
            float hi = (2 * q + 1 < rem) ? p[2 * q + 1] : 0.0f;
            v[q] = pk(lo, hi);
        }
    }
}

// 4 window sums -> 4 abs-deviation sums over a 68-float register segment.
__device__ __forceinline__ void process_seg(const u64 v[2 * CHUNKS], float a[WPT])
{
    // Pass 1: sum of elements [0,64) -- 4 parallel chains of 8.
    u64 t0 = v[0], t1 = v[1], t2a = v[2], t3 = v[3];
    #pragma unroll
    for (int p = 1; p < 8; p++) {
        t0  = addx2(t0,  v[4 * p]);
        t1  = addx2(t1,  v[4 * p + 1]);
        t2a = addx2(t2a, v[4 * p + 2]);
        t3  = addx2(t3,  v[4 * p + 3]);
    }
    u64 acc = addx2(addx2(t0, t1), addx2(t2a, t3));
    float lo, hi; upk(acc, lo, hi);

    float s[WPT];
    s[0] = lo + hi;
    float e0, e1, e2, e3, f0, f1, f2, f3;
    upk(v[0],  e0, e1); upk(v[1],  e2, e3);   // elements 0..3
    upk(v[32], f0, f1); upk(v[33], f2, f3);   // elements 64..67
    const float d0 = f0 - e0;
    const float d1 = f1 - e1;
    const float d2s = f2 - e2;
    s[1] = s[0] + d0;
    s[2] = s[0] + (d0 + d1);
    s[3] = s[0] + ((d0 + d1) + d2s);
    (void)e3; (void)f3;

    const float invk = 1.0f / (float)K_WIN;

    // Pass 2: per window w, sum |x - m| -- 4 parallel chains per window.
    #pragma unroll
    for (int w = 0; w < WPT; w++) {
        const float m = s[w] * invk;
        const u64 nm2 = pk(-m, -m);
        u64 a0 = 0ULL, a1p = 0ULL, a2p = 0ULL, a3p = 0ULL;
        float extra = 0.0f;
        if ((w & 1) == 0) {
            const int p0 = w >> 1;             // 32 aligned pairs
            #pragma unroll
            for (int p = 0; p < 8; p++) {
                a0  = addx2(a0,  absx2(addx2(v[p0 + 4 * p],     nm2)));
                a1p = addx2(a1p, absx2(addx2(v[p0 + 4 * p + 1], nm2)));
                a2p = addx2(a2p, absx2(addx2(v[p0 + 4 * p + 2], nm2)));
                a3p = addx2(a3p, absx2(addx2(v[p0 + 4 * p + 3], nm2)));
            }
        } else {
            const int p0 = (w + 1) >> 1;       // 31 aligned interior pairs
            #pragma unroll
            for (int p = 0; p < 7; p++) {
                a0  = addx2(a0,  absx2(addx2(v[p0 + 4 * p],     nm2)));
                a1p = addx2(a1p, absx2(addx2(v[p0 + 4 * p + 1], nm2)));
                a2p = addx2(a2p, absx2(addx2(v[p0 + 4 * p + 2], nm2)));
                a3p = addx2(a3p, absx2(addx2(v[p0 + 4 * p + 3], nm2)));
            }
            a0  = addx2(a0,  absx2(addx2(v[p0 + 28], nm2)));
            a1p = addx2(a1p, absx2(addx2(v[p0 + 29], nm2)));
            a2p = addx2(a2p, absx2(addx2(v[p0 + 30], nm2)));
            float q0, q1, x0, x1;
            upk(v[w >> 1], q0, q1);        x0 = q1;   // element w (odd -> hi half)
            upk(v[(w + 63) >> 1], q0, q1); x1 = q0;   // element w+63 (even -> lo half)
            extra = fabsf(x0 - m) + fabsf(x1 - m);
        }
        u64 aa = addx2(addx2(a0, a1p), addx2(a2p, a3p));
        float al, ah; upk(aa, al, ah);
        a[w] = (al + ah) + extra;
    }
}

__global__ void __launch_bounds__(BLOCK, 2)
smoothness_persist_kernel(const float* __restrict__ yh,
                          const float* __restrict__ yy,
                          int W, int N, int WB,
                          float* __restrict__ out, double invW)
{
    __shared__ float  redf[BLOCK / 32];
    __shared__ double redd[BLOCK / 32];
    __shared__ int    amLast;

    const int tid    = threadIdx.x;
    const int wstart = blockIdx.x * WB;            // multiple of 4
    const int wend   = min(wstart + WB, W);

    float d2 = 0.0f;
    u64 v[2 * CHUNKS];

    for (int i0 = wstart + WPT * tid; i0 < wend; i0 += STRIDE) {
        const int rem = N - i0;
        float a1[WPT], a2[WPT];

        load_seg(yh + i0, rem, v);
        process_seg(v, a1);
        load_seg(yy + i0, rem, v);
        process_seg(v, a2);

        #pragma unroll
        for (int w = 0; w < WPT; w++) {
            if (i0 + w < wend) {
                const float d = a1[w] - a2[w];
                d2 += d * d;
            }
        }
    }

    // Block reduction of d2.
    #pragma unroll
    for (int off = 16; off > 0; off >>= 1)
        d2 += __shfl_down_sync(0xffffffffu, d2, off);

    const int lane = tid & 31, wid = tid >> 5;
    if (lane == 0) redf[wid] = d2;
    __syncthreads();
    if (wid == 0) {
        float vv = (lane < BLOCK / 32) ? redf[lane] : 0.0f;
        #pragma unroll
        for (int off = 4; off > 0; off >>= 1)
            vv += __shfl_down_sync(0xffffffffu, vv, off);
        if (lane == 0) {
            g_partials[blockIdx.x] = vv;
            __threadfence();
            unsigned int c = atomicAdd(&g_count, 1u);
            amLast = (c == (unsigned int)(gridDim.x - 1));
        }
    }
    __syncthreads();

    if (amLast) {
        // Deterministic final reduction (fixed order/topology).
        double s = 0.0;
        for (int i = tid; i < GRID; i += BLOCK)
            s += (double)g_partials[i];
        #pragma unroll
        for (int off = 16; off > 0; off >>= 1)
            s += __shfl_down_sync(0xffffffffu, s, off);
        if (lane == 0) redd[wid] = s;
        __syncthreads();
        if (wid == 0) {
            double vv = (lane < BLOCK / 32) ? redd[lane] : 0.0;
            #pragma unroll
            for (int off = 4; off > 0; off >>= 1)
                vv += __shfl_down_sync(0xffffffffu, vv, off);
            if (lane == 0) {
                out[0] = (float)(vv * invW);
                g_count = 0;                 // reset for next graph replay
            }
        }
    }
}

extern "C" void kernel_launch(void* const* d_in, const int* in_sizes, int n_in,
                              void* d_out, int out_size)
{
    const float* yh = (const float*)d_in[0];
    const float* yy = (const float*)d_in[1];
    const int N = in_sizes[0];
    const int W = N - K_WIN - 1;
    int WB = (W + GRID - 1) / GRID;
    WB = (WB + 3) & ~3;

    smoothness_persist_kernel<<<GRID, BLOCK>>>(yh, yy, W, N, WB,
                                               (float*)d_out, 1.0 / (double)W);
}

// round 6
// speedup vs baseline: 1.0091x; 1.0091x over previous
#include <cuda_runtime.h>
#include <cuda_bf16.h>

// SmoothnessLoss: loss = mean_i( (sHat_i - sY_i)^2 ), i in [0, W), W = N-k-1
// s_i = sum_{j<k} | x[i+j] - mean_j |, k = 64.
// Persistent kernel, register-lean two-pass streaming (pass2 re-reads via L1),
// 3 blocks/SM for occupancy. Fused deterministic final reduction.

#define K_WIN 64
#define BLOCK 256
#define WPT 4
#define STRIDE (BLOCK * WPT)                 // 1024 windows per block-iteration
#define GRID 444                             // 3 blocks/SM x 148 SMs

typedef unsigned long long u64;

__device__ float g_partials[GRID];
__device__ unsigned int g_count = 0;

__device__ __forceinline__ u64 addx2(u64 a, u64 b) {
    u64 r; asm("add.rn.f32x2 %0, %1, %2;" : "=l"(r) : "l"(a), "l"(b)); return r;
}
__device__ __forceinline__ u64 pk(float lo, float hi) {
    u64 r; asm("mov.b64 %0, {%1, %2};" : "=l"(r) : "f"(lo), "f"(hi)); return r;
}
__device__ __forceinline__ void upk(u64 p, float& lo, float& hi) {
    asm("mov.b64 {%0, %1}, %2;" : "=f"(lo), "=f"(hi) : "l"(p));
}
__device__ __forceinline__ u64 absx2(u64 a) { return a & 0x7FFFFFFF7FFFFFFFULL; }
__device__ __forceinline__ float sum2(u64 a) { float l, h; upk(a, l, h); return l + h; }

// Opaque 16B load (prevents CSE with pass-1 loads; L1 hit expected).
__device__ __forceinline__ void ldg2(const ulonglong2* p, u64& x, u64& y) {
    asm volatile("ld.global.nc.v2.u64 {%0, %1}, [%2];"
                 : "=l"(x), "=l"(y) : "l"(p));
}

// Fast path: 4 windows over a fully in-bounds 68-float segment (16B-aligned).
__device__ __forceinline__ void seg_windows_packed(const float* __restrict__ p,
                                                   float a[WPT])
{
    const ulonglong2* p2 = reinterpret_cast<const ulonglong2*>(p);

    // ---- Pass 1: mean sums (stream chunks through 4 chains) ----
    ulonglong2 c0 = p2[0];
    ulonglong2 cb1 = p2[1];
    u64 t0 = c0.x, t1 = c0.y, t2 = cb1.x, t3 = cb1.y;
    #pragma unroll
    for (int c = 2; c < 16; c += 2) {
        ulonglong2 ca = p2[c];
        ulonglong2 cb = p2[c + 1];
        t0 = addx2(t0, ca.x);
        t1 = addx2(t1, ca.y);
        t2 = addx2(t2, cb.x);
        t3 = addx2(t3, cb.y);
    }
    ulonglong2 c16 = p2[16];

    float lo, hi; upk(addx2(addx2(t0, t1), addx2(t2, t3)), lo, hi);
    float e0, e1, e2, e3, f0, f1, f2, f3;
    upk(c0.x, e0, e1); upk(c0.y, e2, e3);     // elements 0..3
    upk(c16.x, f0, f1); upk(c16.y, f2, f3);   // elements 64..67
    (void)f3;

    const float invk = 1.0f / (float)K_WIN;
    const float s0 = lo + hi;
    const float d0 = f0 - e0, d1 = f1 - e1, d2s = f2 - e2;
    float m0 = s0 * invk;
    float m1 = (s0 + d0) * invk;
    float m2 = (s0 + (d0 + d1)) * invk;
    float m3 = (s0 + ((d0 + d1) + d2s)) * invk;
    const u64 nm0 = pk(-m0, -m0);
    const u64 nm1 = pk(-m1, -m1);
    const u64 nm2 = pk(-m2, -m2);
    const u64 nm3 = pk(-m3, -m3);

    // ---- Pass 2: abs-deviation sums, chunk-major (re-load interior via L1) ----
    u64 aA0 = 0, aB0 = 0, aA1 = 0, aB1 = 0;
    u64 aA2 = 0, aB2 = 0, aA3 = 0, aB3 = 0;
    #pragma unroll
    for (int c = 1; c < 16; c++) {            // pairs 2..31: in all 4 windows
        u64 cx, cy;
        ldg2(p2 + c, cx, cy);
        aA0 = addx2(aA0, absx2(addx2(cx, nm0)));
        aB0 = addx2(aB0, absx2(addx2(cy, nm0)));
        aA1 = addx2(aA1, absx2(addx2(cx, nm1)));
        aB1 = addx2(aB1, absx2(addx2(cy, nm1)));
        aA2 = addx2(aA2, absx2(addx2(cx, nm2)));
        aB2 = addx2(aB2, absx2(addx2(cy, nm2)));
        aA3 = addx2(aA3, absx2(addx2(cx, nm3)));
        aB3 = addx2(aB3, absx2(addx2(cy, nm3)));
    }
    // Boundary pairs/elements (window w covers [w, w+64)):
    aA0 = addx2(aA0, absx2(addx2(c0.x, nm0)));    // pair 0 -> w0
    aB0 = addx2(aB0, absx2(addx2(c0.y, nm0)));    // pair 1 -> w0
    aA1 = addx2(aA1, absx2(addx2(c0.y, nm1)));    // pair 1 -> w1
    aA2 = addx2(aA2, absx2(addx2(c0.y, nm2)));    // pair 1 -> w2
    aB2 = addx2(aB2, absx2(addx2(c16.x, nm2)));   // pair 32 -> w2
    aA3 = addx2(aA3, absx2(addx2(c16.x, nm3)));   // pair 32 -> w3
    const float ex1 = fabsf(e1 - m1) + fabsf(f0 - m1);   // elements 1, 64
    const float ex3 = fabsf(e3 - m3) + fabsf(f2 - m3);   // elements 3, 66

    a[0] = sum2(addx2(aA0, aB0));
    a[1] = sum2(addx2(aA1, aB1)) + ex1;
    a[2] = sum2(addx2(aA2, aB2));
    a[3] = sum2(addx2(aA3, aB3)) + ex3;
}

// Rare tail fallback (segment not fully in-bounds). Low register use.
__device__ void seg_windows_scalar(const float* __restrict__ p, int rem, float a[WPT])
{
    #pragma unroll 1
    for (int w = 0; w < WPT; w++) {
        float s = 0.0f;
        #pragma unroll 1
        for (int j = 0; j < K_WIN; j++) {
            const int idx = w + j;
            s += (idx < rem) ? p[idx] : 0.0f;
        }
        const float m = s * (1.0f / (float)K_WIN);
        float t = 0.0f;
        #pragma unroll 1
        for (int j = 0; j < K_WIN; j++) {
            const int idx = w + j;
            const float x = (idx < rem) ? p[idx] : 0.0f;
            t += fabsf(x - m);
        }
        a[w] = t;
    }
}

__global__ void __launch_bounds__(BLOCK, 3)
smoothness_persist_kernel(const float* __restrict__ yh,
                          const float* __restrict__ yy,
                          int W, int N, int WB,
                          float* __restrict__ out, double invW)
{
    __shared__ float  redf[BLOCK / 32];
    __shared__ double redd[BLOCK / 32];
    __shared__ int    amLast;

    const int tid    = threadIdx.x;
    const int wstart = blockIdx.x * WB;            // multiple of 4
    const int wend   = min(wstart + WB, W);

    float d2 = 0.0f;

    for (int i0 = wstart + WPT * tid; i0 < wend; i0 += STRIDE) {
        float a1[WPT], a2[WPT];
        if (N - i0 >= 68) {
            seg_windows_packed(yh + i0, a1);
            seg_windows_packed(yy + i0, a2);
        } else {
            seg_windows_scalar(yh + i0, N - i0, a1);
            seg_windows_scalar(yy + i0, N - i0, a2);
        }
        if (i0 + WPT <= wend) {
            #pragma unroll
            for (int w = 0; w < WPT; w++) {
                const float d = a1[w] - a2[w];
                d2 += d * d;
            }
        } else {
            #pragma unroll
            for (int w = 0; w < WPT; w++) {
                if (i0 + w < wend) {
                    const float d = a1[w] - a2[w];
                    d2 += d * d;
                }
            }
        }
    }

    // Block reduction of d2.
    #pragma unroll
    for (int off = 16; off > 0; off >>= 1)
        d2 += __shfl_down_sync(0xffffffffu, d2, off);

    const int lane = tid & 31, wid = tid >> 5;
    if (lane == 0) redf[wid] = d2;
    __syncthreads();
    if (wid == 0) {
        float vv = (lane < BLOCK / 32) ? redf[lane] : 0.0f;
        #pragma unroll
        for (int off = 4; off > 0; off >>= 1)
            vv += __shfl_down_sync(0xffffffffu, vv, off);
        if (lane == 0) {
            g_partials[blockIdx.x] = vv;
            __threadfence();
            unsigned int c = atomicAdd(&g_count, 1u);
            amLast = (c == (unsigned int)(gridDim.x - 1));
        }
    }
    __syncthreads();

    if (amLast) {
        // Deterministic final reduction (fixed order/topology).
        double s = 0.0;
        for (int i = tid; i < GRID; i += BLOCK)
            s += (double)g_partials[i];
        #pragma unroll
        for (int off = 16; off > 0; off >>= 1)
            s += __shfl_down_sync(0xffffffffu, s, off);
        if (lane == 0) redd[wid] = s;
        __syncthreads();
        if (wid == 0) {
            double vv = (lane < BLOCK / 32) ? redd[lane] : 0.0;
            #pragma unroll
            for (int off = 4; off > 0; off >>= 1)
                vv += __shfl_down_sync(0xffffffffu, vv, off);
            if (lane == 0) {
                out[0] = (float)(vv * invW);
                g_count = 0;                 // reset for next graph replay
            }
        }
    }
}

extern "C" void kernel_launch(void* const* d_in, const int* in_sizes, int n_in,
                              void* d_out, int out_size)
{
    const float* yh = (const float*)d_in[0];
    const float* yy = (const float*)d_in[1];
    const int N = in_sizes[0];
    const int W = N - K_WIN - 1;
    int WB = (W + GRID - 1) / GRID;
    WB = (WB + 3) & ~3;

    smoothness_persist_kernel<<<GRID, BLOCK>>>(yh, yy, W, N, WB,
                                               (float*)d_out, 1.0 / (double)W);
}